// round 17
// baseline (speedup 1.0000x reference)
#include <cuda_runtime.h>
#include <cuda_bf16.h>
#include <math.h>

#define BB 32
#define TT 256
#define EE 256
#define HHD 256
#define KK 12
#define TSTART 10
#define TSTOP 11
#define NEGV (-10000.0f)

// h row stride in smem (padded to kill 4-row bank aliasing)
#define HSTR 260
#define WS_FLOATS 32768                 // 32 u x 4 gates x 256 v
#define HB_FLOATS (2 * 4 * HSTR)        // double-buffered 4 batches x 256(+pad)
#define LSTM_SMEM ((WS_FLOATS + HB_FLOATS) * 4)

// ------------------- static device scratch -------------------
__device__ float g_G2[2][TT][BB][1024];         // gate pre-activations [dir][t][b][jg], jg=g*256+u
__device__ float g_Hcat[BB][TT][512];           // concatenated hidden states
__device__ float g_feats[BB][TT][KK];           // emission features

// ------------------- fused gather + input-projection GEMM -------------------
// g_G2[dir][t][b][jg] = emb[tok(t,b,dir)] . Wih[jg,:] + bih[jg] + bhh[jg]
#define GP 68
__global__ void k_gemm(const int* __restrict__ sent, const int* __restrict__ lens,
                       const float* __restrict__ emb,
                       const float* __restrict__ Wf, const float* __restrict__ Wb,
                       const float* __restrict__ bihf, const float* __restrict__ bhhf,
                       const float* __restrict__ bihb, const float* __restrict__ bhhb) {
    __shared__ __align__(16) float Xs[16][GP];
    __shared__ __align__(16) float Ws[16][GP];
    __shared__ int toks[64];
    int dir  = blockIdx.z;
    int row0 = blockIdx.y * 64;
    int j0   = blockIdx.x * 64;
    const float* W = dir ? Wb : Wf;
    int tid = threadIdx.x;             // 256
    int tx = tid & 15, ty = tid >> 4;
    int lk = tid & 15, lr = tid >> 4;

    if (tid < 64) {
        int row = row0 + tid;
        int t = row >> 5, b = row & 31;
        int len = lens[b];
        int pos = dir ? ((t < len) ? (len - 1 - t) : t) : t;
        toks[tid] = sent[b * TT + pos];
    }
    __syncthreads();
    int myrow[4];
#pragma unroll
    for (int it = 0; it < 4; it++) myrow[it] = toks[lr + it * 16];

    float acc[4][4];
#pragma unroll
    for (int i = 0; i < 4; i++)
#pragma unroll
        for (int j = 0; j < 4; j++) acc[i][j] = 0.f;

    for (int k0 = 0; k0 < 256; k0 += 16) {
        __syncthreads();
#pragma unroll
        for (int it = 0; it < 4; it++) {
            int r = lr + it * 16;
            Xs[lk][r] = emb[myrow[it] * EE + k0 + lk];
            Ws[lk][r] = W[(j0 + r) * EE + k0 + lk];
        }
        __syncthreads();
#pragma unroll
        for (int kk = 0; kk < 16; kk++) {
            float4 xa = *(const float4*)&Xs[kk][ty * 4];
            float4 wb = *(const float4*)&Ws[kk][tx * 4];
            float xr[4] = {xa.x, xa.y, xa.z, xa.w};
            float wr[4] = {wb.x, wb.y, wb.z, wb.w};
#pragma unroll
            for (int i = 0; i < 4; i++)
#pragma unroll
                for (int j = 0; j < 4; j++) acc[i][j] += xr[i] * wr[j];
        }
    }
    // epilogue: add biases (float4), coalesced STG.128 per row
    int jg0 = j0 + tx * 4;
    float4 bi = dir ? *(const float4*)&bihb[jg0] : *(const float4*)&bihf[jg0];
    float4 bh = dir ? *(const float4*)&bhhb[jg0] : *(const float4*)&bhhf[jg0];
    float4 bs = make_float4(bi.x + bh.x, bi.y + bh.y, bi.z + bh.z, bi.w + bh.w);
#pragma unroll
    for (int i = 0; i < 4; i++) {
        int row = row0 + ty * 4 + i;
        int t = row >> 5, b = row & 31;
        float4 v = make_float4(acc[i][0] + bs.x, acc[i][1] + bs.y,
                               acc[i][2] + bs.z, acc[i][3] + bs.w);
        *(float4*)&g_G2[dir][t][b][jg0] = v;
    }
}

// ------------------- persistent recurrent LSTM: 8-CTA clusters + DSMEM -----
// 128 blocks in 16 clusters of 8. Cluster = (dir, batch-group of 4).
// Rank r owns u in [r*32, r*32+32). h exchanged via st.shared::cluster,
// ordered by one barrier.cluster per step.
__device__ __forceinline__ float fsig(float x) { return 1.f / (1.f + __expf(-x)); }

__global__ void __launch_bounds__(128, 1) __cluster_dims__(8, 1, 1)
k_lstm(const float* __restrict__ Whhf, const float* __restrict__ Whhb,
       const float* __restrict__ h0, const float* __restrict__ c0,
       const int* __restrict__ lens) {
    extern __shared__ __align__(16) float sm[];   // ws[32768] + hbuf[2][4][HSTR]
    float* ws = sm;
    float* hbuf = sm + WS_FLOATS;

    int bid  = blockIdx.x;
    int ci   = bid >> 3;               // cluster 0..15
    int rank = bid & 7;
    int dir  = ci >> 3;                // 0..1
    int b0   = (ci & 7) * 4;           // batch group
    int u0   = rank * 32;
    int tid  = threadIdx.x;            // 128
    int u_l  = tid >> 2;               // 0..31  (warp spans 8 u -> w broadcast dedup)
    int b_l  = tid & 3;                // 0..3
    int u = u0 + u_l;
    int b = b0 + b_l;
    const float* Whh = dir ? Whhb : Whhf;

    // stage Whh slice: ws[v*128 + ul*4 + g] = Whh[(g*256 + u0 + ul)*256 + v]
    for (int i = tid; i < WS_FLOATS; i += 128) {
        int v = i & 255;
        int r = i >> 8;                  // ul*4 + g
        int ul = r >> 2, g = r & 3;
        ws[v * 128 + ul * 4 + g] = Whh[(g * 256 + u0 + ul) * HHD + v];
    }
    // h0 into parity-0 buffer (each CTA keeps a full local copy for its 4 batches)
    for (int i = tid; i < 1024; i += 128) {
        int bb = i >> 8, vv = i & 255;
        hbuf[bb * HSTR + vv] = h0[(dir * BB + b0 + bb) * HHD + vv];
    }
    float c = c0[(dir * BB + b) * HHD + u];
    int len = lens[b];

    // shared-window base (u32) and peer base addresses via mapa
    unsigned sbase;
    asm("{ .reg .u64 t; cvta.to.shared.u64 t, %1; cvt.u32.u64 %0, t; }"
        : "=r"(sbase) : "l"(sm));
    unsigned raddr[8];
#pragma unroll
    for (int rr = 0; rr < 8; rr++) {
        asm("mapa.shared::cluster.u32 %0, %1, %2;"
            : "=r"(raddr[rr]) : "r"(sbase), "r"(rr));
    }
    unsigned slot = (unsigned)(b_l * HSTR + u) * 4u + WS_FLOATS * 4u;  // byte off, parity 0
    __syncthreads();

    for (int t = 0; t < TT; t++) {
        // prefetch gate pre-activations (independent of h, in flight across barrier)
        const float* gbase = &g_G2[dir][t][b][0];
        float gp0 = __ldg(gbase + u);
        float gp1 = __ldg(gbase + 256 + u);
        float gp2 = __ldg(gbase + 512 + u);
        float gp3 = __ldg(gbase + 768 + u);

        // cluster barrier: peers' step-(t-1) DSMEM h-writes visible after this
        asm volatile("barrier.cluster.arrive.aligned;\n\t"
                     "barrier.cluster.wait.aligned;" ::: "memory");

        int par = t & 1;
        const float* hrow = hbuf + par * (4 * HSTR) + b_l * HSTR;

        // GEMV: 4 gates x 256 (FFMA-bound; w broadcast-dedup'd 4x in-warp)
        float ai = 0.f, af = 0.f, ag = 0.f, ao = 0.f;
#pragma unroll 8
        for (int v = 0; v < 256; v += 4) {
            float4 h4 = *(const float4*)&hrow[v];
            float4 w0 = *(const float4*)&ws[(v + 0) * 128 + u_l * 4];
            float4 w1 = *(const float4*)&ws[(v + 1) * 128 + u_l * 4];
            float4 w2 = *(const float4*)&ws[(v + 2) * 128 + u_l * 4];
            float4 w3 = *(const float4*)&ws[(v + 3) * 128 + u_l * 4];
            ai += w0.x * h4.x; af += w0.y * h4.x; ag += w0.z * h4.x; ao += w0.w * h4.x;
            ai += w1.x * h4.y; af += w1.y * h4.y; ag += w1.z * h4.y; ao += w1.w * h4.y;
            ai += w2.x * h4.z; af += w2.y * h4.z; ag += w2.z * h4.z; ao += w2.w * h4.z;
            ai += w3.x * h4.w; af += w3.y * h4.w; ag += w3.z * h4.w; ao += w3.w * h4.w;
        }
        ai += gp0; af += gp1; ag += gp2; ao += gp3;
        float ig = fsig(ai), fg = fsig(af), gg = tanhf(ag), og = fsig(ao);
        c = fg * c + ig * gg;
        float h = og * tanhf(c);

        // broadcast my h to all 8 cluster CTAs' parity^1 buffer (disjoint slots)
        unsigned off = slot + (unsigned)((par ^ 1) * (4 * HSTR) * 4);
        unsigned hv = __float_as_uint(h);
#pragma unroll
        for (int rr = 0; rr < 8; rr++) {
            asm volatile("st.shared::cluster.b32 [%0], %1;"
                         :: "r"(raddr[rr] + off), "r"(hv) : "memory");
        }

        int pos = dir ? ((t < len) ? (len - 1 - t) : t) : t;
        g_Hcat[b][pos][dir * 256 + u] = h;
    }
    // don't exit while peers may still be writing into our smem
    asm volatile("barrier.cluster.arrive.aligned;\n\t"
                 "barrier.cluster.wait.aligned;" ::: "memory");
}

// ------------------- emission features: Hcat @ W_out^T + b_out -------------------
__global__ void k_feats(const float* __restrict__ Wout, const float* __restrict__ bout) {
    __shared__ __align__(16) float Wsh[12 * 516];
    __shared__ __align__(16) float Hsh[8 * 516];
    int blk = blockIdx.x;              // 1024 blocks, 8 rows each
    int tid = threadIdx.x;             // 128
    for (int i = tid; i < 12 * 512; i += 128) Wsh[(i >> 9) * 516 + (i & 511)] = Wout[i];
    int row0 = blk * 8;                // row = b*256 + t
    for (int i = tid; i < 8 * 512; i += 128)
        Hsh[(i >> 9) * 516 + (i & 511)] = ((const float*)g_Hcat)[(row0 + (i >> 9)) * 512 + (i & 511)];
    __syncthreads();
    if (tid < 96) {
        int rl = tid / 12, k = tid % 12;
        float s0 = bout[k], s1 = 0.f, s2 = 0.f, s3 = 0.f;
        const float* wr = &Wsh[k * 516];
        const float* hr = &Hsh[rl * 516];
#pragma unroll 8
        for (int hh = 0; hh < 512; hh += 4) {
            float4 a = *(const float4*)&wr[hh];
            float4 bb4 = *(const float4*)&hr[hh];
            s0 += a.x * bb4.x; s1 += a.y * bb4.y; s2 += a.z * bb4.z; s3 += a.w * bb4.w;
        }
        ((float*)g_feats)[(row0 + rl) * 12 + k] = (s0 + s1) + (s2 + s3);
    }
}

// ------------------- Viterbi DP + backtrace -------------------
__global__ void k_viterbi(const float* __restrict__ trans, const int* __restrict__ lens,
                          float* __restrict__ out) {
    __shared__ float tr[144];
    __shared__ float fv[8][13];
    __shared__ unsigned char bp[TT][8][12];
    __shared__ int lsh[8];
    int b0 = blockIdx.x * 8;
    int tid = threadIdx.x;             // 128
    for (int i = tid; i < 144; i += 128) tr[i] = trans[i];
    if (tid < 8) lsh[tid] = lens[b0 + tid];
    int rl = tid / 12, k = tid % 12;
    bool act = tid < 96;
    if (act) fv[rl][k] = (k == TSTART) ? 0.f : NEGV;
    __syncthreads();

    float trk[12];
    if (act) {
#pragma unroll
        for (int p = 0; p < 12; p++) trk[p] = tr[k * 12 + p];
    }
    int len = act ? lsh[rl] : 0;
    int bg = b0 + rl;

    for (int t = 0; t < TT; t++) {
        float nf = 0.f;
        if (act) {
            float feat = ((const float*)g_feats)[(bg * TT + t) * 12 + k];
            float best = fv[rl][0] + trk[0];
            int bpi = 0;
#pragma unroll
            for (int p = 1; p < 12; p++) {
                float s = fv[rl][p] + trk[p];
                if (s > best) { best = s; bpi = p; }   // strict > => first max (jnp.argmax)
            }
            bp[t][rl][k] = (unsigned char)bpi;
            nf = (t < len) ? (best + feat) : fv[rl][k];
        }
        __syncthreads();
        if (act) fv[rl][k] = nf;
        __syncthreads();
    }

    if (tid < 8) {
        int r = tid;
        int bgl = b0 + r;
        int ln = lsh[r];
        float best = fv[r][0] + tr[TSTOP * 12 + 0];
        int tag = 0;
        for (int p = 1; p < 12; p++) {
            float s = fv[r][p] + tr[TSTOP * 12 + p];
            if (s > best) { best = s; tag = p; }
        }
        out[bgl] = best;                               // path score
        for (int t = TT - 1; t >= 0; t--) {
            bool m = t < ln;
            out[BB + bgl * TT + t] = m ? (float)tag : -1.0f;
            if (m) tag = bp[t][r][tag];
        }
    }
}

// ------------------- launch -------------------
extern "C" void kernel_launch(void* const* d_in, const int* in_sizes, int n_in,
                              void* d_out, int out_size) {
    const int*   sent  = (const int*)d_in[0];
    const int*   lens  = (const int*)d_in[1];
    const float* emb   = (const float*)d_in[2];
    const float* Wihf  = (const float*)d_in[3];
    const float* Whhf  = (const float*)d_in[4];
    const float* bihf  = (const float*)d_in[5];
    const float* bhhf  = (const float*)d_in[6];
    const float* Wihb  = (const float*)d_in[7];
    const float* Whhb  = (const float*)d_in[8];
    const float* bihb  = (const float*)d_in[9];
    const float* bhhb  = (const float*)d_in[10];
    const float* h0    = (const float*)d_in[11];
    const float* c0    = (const float*)d_in[12];
    const float* Wout  = (const float*)d_in[13];
    const float* bout  = (const float*)d_in[14];
    const float* trans = (const float*)d_in[15];
    float* out = (float*)d_out;

    static int attr_set = 0;
    if (!attr_set) {
        cudaFuncSetAttribute(k_lstm, cudaFuncAttributeMaxDynamicSharedMemorySize, LSTM_SMEM);
        attr_set = 1;
    }

    dim3 gg(16, 128, 2);
    k_gemm<<<gg, 256>>>(sent, lens, emb, Wihf, Wihb, bihf, bhhf, bihb, bhhb);
    k_lstm<<<128, 128, LSTM_SMEM>>>(Whhf, Whhb, h0, c0, lens);
    k_feats<<<1024, 128>>>(Wout, bout);
    k_viterbi<<<4, 128>>>(trans, lens, out);
}